// round 3
// baseline (speedup 1.0000x reference)
#include <cuda_runtime.h>

// CosineSim3D: out[b,n,:300] = softmax_n( (a_n . sum_m b_m/|b_m|) / |a_n| )
// B=128, N=M=1024, D=300. Three full-chip streaming passes.

static constexpr int BATCH = 128;
static constexpr int NROW  = 1024;
static constexpr int DDIM  = 300;
static constexpr int NQ    = 75;    // float4 per row
static constexpr int DPAD  = 304;   // padded feature dim (16B multiple)
static constexpr int PB    = 8;     // partitions per batch
static constexpr int RPP   = NROW / PB;        // 128 rows per partition/block
static constexpr int THREADS = 256;
static constexpr int WARPS   = 8;
static constexpr int RPW     = RPP / WARPS;    // 16 rows per warp
static constexpr int RPI     = 2;              // rows per load-batch

#define EPSV 1e-7f

// scratch (no allocations allowed)
__device__ float g_bpart[BATCH][PB][DPAD];
__device__ float g_scores[BATCH][NROW];

__device__ __forceinline__ float warp_sum(float v) {
    #pragma unroll
    for (int o = 16; o > 0; o >>= 1) v += __shfl_xor_sync(0xffffffffu, v, o);
    return v;
}
__device__ __forceinline__ float warp_max(float v) {
    #pragma unroll
    for (int o = 16; o > 0; o >>= 1) v = fmaxf(v, __shfl_xor_sync(0xffffffffu, v, o));
    return v;
}
__device__ __forceinline__ float dot4(float4 x, float4 y) {
    return fmaf(x.x, y.x, fmaf(x.y, y.y, fmaf(x.z, y.z, x.w * y.w)));
}
__device__ __forceinline__ void axpy4(float4& acc, float4 q, float s) {
    acc.x = fmaf(q.x, s, acc.x);
    acc.y = fmaf(q.y, s, acc.y);
    acc.z = fmaf(q.z, s, acc.z);
    acc.w = fmaf(q.w, s, acc.w);
}

// ---------------- K1: partial bsum = sum over 128 b-rows of b_m / ||b_m|| ----
__global__ void __launch_bounds__(THREADS)
k1_bsum(const float* __restrict__ gb)
{
    __shared__ __align__(16) float s_part[WARPS][DPAD];

    const int batch = blockIdx.x / PB;
    const int part  = blockIdx.x % PB;
    const int tid   = threadIdx.x;
    const int wid   = tid >> 5;
    const int lane  = tid & 31;
    const bool has_q2 = lane < (NQ - 64);  // lane < 11

    const float4* b4 = reinterpret_cast<const float4*>(gb) + (size_t)batch * NROW * NQ;
    const int rbase = part * RPP + wid * RPW;
    const float4 f4z = make_float4(0.f, 0.f, 0.f, 0.f);

    float4 acc0 = f4z, acc1 = f4z, acc2 = f4z;

    #pragma unroll 1
    for (int i = 0; i < RPW; i += RPI) {
        float4 q0[RPI], q1[RPI], q2[RPI];
        #pragma unroll
        for (int r = 0; r < RPI; r++) {
            const float4* row = b4 + (size_t)(rbase + i + r) * NQ;
            q0[r] = row[lane];
            q1[r] = row[lane + 32];
            q2[r] = has_q2 ? row[lane + 64] : f4z;
        }
        #pragma unroll
        for (int r = 0; r < RPI; r++) {
            float ss = dot4(q0[r], q0[r]) + dot4(q1[r], q1[r]) + dot4(q2[r], q2[r]);
            ss = warp_sum(ss);
            float inv = 1.0f / sqrtf(fmaxf(ss, EPSV));
            axpy4(acc0, q0[r], inv);
            axpy4(acc1, q1[r], inv);
            axpy4(acc2, q2[r], inv);
        }
    }

    {
        float4* p4 = reinterpret_cast<float4*>(&s_part[wid][0]);
        p4[lane]      = acc0;
        p4[lane + 32] = acc1;
        if (has_q2) p4[lane + 64] = acc2;
    }
    __syncthreads();

    // thread-count-agnostic cross-warp reduce (BUGFIX: DDIM > THREADS subset)
    for (int d = tid; d < DDIM; d += THREADS) {
        float s = 0.f;
        #pragma unroll
        for (int w = 0; w < WARPS; w++) s += s_part[w][d];
        g_bpart[batch][part][d] = s;
    }
}

// ---------------- K2: scores[n] = (a_n . bsum) / ||a_n|| ---------------------
__global__ void __launch_bounds__(THREADS)
k2_scores(const float* __restrict__ ga)
{
    __shared__ __align__(16) float s_bsum[DPAD];

    const int batch = blockIdx.x / PB;
    const int part  = blockIdx.x % PB;
    const int tid   = threadIdx.x;
    const int wid   = tid >> 5;
    const int lane  = tid & 31;
    const bool has_q2 = lane < (NQ - 64);

    // thread-count-agnostic reduce of 8 partials (BUGFIX)
    for (int d = tid; d < DDIM; d += THREADS) {
        float s = 0.f;
        #pragma unroll
        for (int p = 0; p < PB; p++) s += g_bpart[batch][p][d];
        s_bsum[d] = s;
    }
    __syncthreads();

    const float4 f4z = make_float4(0.f, 0.f, 0.f, 0.f);
    float4 bs0, bs1, bs2;
    {
        const float4* bsum4 = reinterpret_cast<const float4*>(s_bsum);
        bs0 = bsum4[lane];
        bs1 = bsum4[lane + 32];
        bs2 = has_q2 ? bsum4[lane + 64] : f4z;
    }

    const float4* a4 = reinterpret_cast<const float4*>(ga) + (size_t)batch * NROW * NQ;
    const int rbase = part * RPP + wid * RPW;

    #pragma unroll 1
    for (int i = 0; i < RPW; i += RPI) {
        float4 q0[RPI], q1[RPI], q2[RPI];
        #pragma unroll
        for (int r = 0; r < RPI; r++) {
            const float4* row = a4 + (size_t)(rbase + i + r) * NQ;
            q0[r] = row[lane];
            q1[r] = row[lane + 32];
            q2[r] = has_q2 ? row[lane + 64] : f4z;
        }
        #pragma unroll
        for (int r = 0; r < RPI; r++) {
            float ss = dot4(q0[r], q0[r]) + dot4(q1[r], q1[r]) + dot4(q2[r], q2[r]);
            float dt = dot4(q0[r], bs0) + dot4(q1[r], bs1) + dot4(q2[r], bs2);
            #pragma unroll
            for (int o = 16; o > 0; o >>= 1) {
                ss += __shfl_xor_sync(0xffffffffu, ss, o);
                dt += __shfl_xor_sync(0xffffffffu, dt, o);
            }
            if (lane == 0)
                g_scores[batch][rbase + i + r] = dt / sqrtf(fmaxf(ss, EPSV));
        }
    }
}

// ---------------- K3: softmax (recomputed per block, deterministic) + write --
__global__ void __launch_bounds__(THREADS)
k3_write(float* __restrict__ gout)
{
    __shared__ __align__(16) float s_scores[NROW];
    __shared__ float s_red[WARPS];

    const int batch = blockIdx.x / PB;
    const int part  = blockIdx.x % PB;
    const int tid   = threadIdx.x;
    const int wid   = tid >> 5;
    const int lane  = tid & 31;
    const bool has_q2 = lane < (NQ - 64);

    // load all 1024 scores for this batch (L2-resident after K2)
    float4 v = reinterpret_cast<const float4*>(&g_scores[batch][0])[tid];
    reinterpret_cast<float4*>(s_scores)[tid] = v;

    // block max (fixed order -> deterministic)
    float mx = fmaxf(fmaxf(v.x, v.y), fmaxf(v.z, v.w));
    mx = warp_max(mx);
    if (lane == 0) s_red[wid] = mx;
    __syncthreads();
    if (wid == 0) {
        float m = (lane < WARPS) ? s_red[lane] : -3.4e38f;
        m = warp_max(m);
        if (lane == 0) s_red[0] = m;
    }
    __syncthreads();
    const float gmx = s_red[0];
    __syncthreads();

    // block sum of exp
    float es = __expf(v.x - gmx) + __expf(v.y - gmx) +
               __expf(v.z - gmx) + __expf(v.w - gmx);
    es = warp_sum(es);
    if (lane == 0) s_red[wid] = es;
    __syncthreads();
    if (wid == 0) {
        float s = (lane < WARPS) ? s_red[lane] : 0.f;
        s = warp_sum(s);
        if (lane == 0) s_red[0] = s;
    }
    __syncthreads();
    const float inv_sum = 1.0f / s_red[0];

    // broadcast-write this partition's 128 rows
    float4* o4 = reinterpret_cast<float4*>(gout) + (size_t)batch * NROW * NQ;
    const int rbase = part * RPP + wid * RPW;

    #pragma unroll 1
    for (int i = 0; i < RPW; i++) {
        const int row = rbase + i;
        const float p = __expf(s_scores[row] - gmx) * inv_sum;
        const float4 pv = make_float4(p, p, p, p);
        float4* orow = o4 + (size_t)row * NQ;
        orow[lane]      = pv;
        orow[lane + 32] = pv;
        if (has_q2) orow[lane + 64] = pv;
    }
}

extern "C" void kernel_launch(void* const* d_in, const int* in_sizes, int n_in,
                              void* d_out, int out_size) {
    const float* a = (const float*)d_in[0];
    const float* b = (const float*)d_in[1];
    float* out = (float*)d_out;
    const int grid = BATCH * PB;
    k1_bsum  <<<grid, THREADS>>>(b);
    k2_scores<<<grid, THREADS>>>(a);
    k3_write <<<grid, THREADS>>>(out);
}